// round 1
// baseline (speedup 1.0000x reference)
#include <cuda_runtime.h>

// SKA forward: out[b, g*16+cg, h, w] = sum_{k=0..8} x_pad[b, g*16+cg, h+di, w+dj] * w[b, cg, k, h, w]
// Shapes: x (16,512,56,56) f32, w (16,16,9,56,56) f32, out (16,512,56,56) f32.
// One thread owns (b, cg, h, w4) -> loads 9 weight float4 into registers once,
// loops over the 32 groups producing a float4 of outputs per group.

#define NB   16
#define NC   512
#define NG   32
#define NCG  16
#define NH   56
#define NW   56
#define NW4  14          // 56 / 4
#define PLANE (NH * NW)  // 3136

__global__ __launch_bounds__(256) void ska_kernel(
    const float* __restrict__ x,
    const float* __restrict__ wt,
    float* __restrict__ out)
{
    const int idx = blockIdx.x * 256 + threadIdx.x;
    if (idx >= NB * NCG * NH * NW4) return;

    const int w4 = idx % NW4;
    int t        = idx / NW4;
    const int h  = t % NH;  t /= NH;
    const int cg = t % NCG;
    const int b  = t / NCG;
    const int col = w4 * 4;

    // ---- load 9 weight float4s once (reused for all 32 groups) ----
    const float* wbase = wt + ((((b * NCG + cg) * 9) * NH + h) * NW + col);
    float4 wk[9];
#pragma unroll
    for (int k = 0; k < 9; ++k)
        wk[k] = *reinterpret_cast<const float4*>(wbase + k * PLANE);

    const bool hm = (h > 0);
    const bool hp = (h < NH - 1);
    const bool wl = (col > 0);
    const bool wr = (col < NW - 4);

    const int chan0 = (b * NC + cg) * PLANE + h * NW + col; // group 0, channel cg
    const float* xc = x + chan0;
    float* oc       = out + chan0;

#pragma unroll 2
    for (int g = 0; g < NG; ++g) {
        const float* xp = xc + g * (NCG * PLANE);
        float4 a = make_float4(0.f, 0.f, 0.f, 0.f);

#pragma unroll
        for (int di = 0; di < 3; ++di) {
            if ((di == 0 && !hm) || (di == 2 && !hp)) continue;
            const float* row = xp + (di - 1) * NW;
            const float4 xm = *reinterpret_cast<const float4*>(row);
            const float  xl = wl ? row[-1] : 0.f;
            const float  xr = wr ? row[4]  : 0.f;

            const float4 w0 = wk[di * 3 + 0];
            const float4 w1 = wk[di * 3 + 1];
            const float4 w2 = wk[di * 3 + 2];

            // dj = -1  (k = di*3+0): x shifted left
            a.x = fmaf(xl,   w0.x, a.x);
            a.y = fmaf(xm.x, w0.y, a.y);
            a.z = fmaf(xm.y, w0.z, a.z);
            a.w = fmaf(xm.z, w0.w, a.w);
            // dj = 0   (k = di*3+1): aligned
            a.x = fmaf(xm.x, w1.x, a.x);
            a.y = fmaf(xm.y, w1.y, a.y);
            a.z = fmaf(xm.z, w1.z, a.z);
            a.w = fmaf(xm.w, w1.w, a.w);
            // dj = +1  (k = di*3+2): x shifted right
            a.x = fmaf(xm.y, w2.x, a.x);
            a.y = fmaf(xm.z, w2.y, a.y);
            a.z = fmaf(xm.w, w2.z, a.z);
            a.w = fmaf(xr,   w2.w, a.w);
        }

        *reinterpret_cast<float4*>(oc + g * (NCG * PLANE)) = a;
    }
}

extern "C" void kernel_launch(void* const* d_in, const int* in_sizes, int n_in,
                              void* d_out, int out_size)
{
    const float* x  = (const float*)d_in[0];
    const float* wt = (const float*)d_in[1];
    float* out      = (float*)d_out;

    const int total  = NB * NCG * NH * NW4; // 200704 threads
    const int blocks = (total + 255) / 256; // 784
    ska_kernel<<<blocks, 256>>>(x, wt, out);
}

// round 2
// speedup vs baseline: 1.4824x; 1.4824x over previous
#include <cuda_runtime.h>

// SKA forward: out[b, g*16+cg, h, w] = sum_{k=0..8} x_pad[b, g*16+cg, h+di, w+dj] * w[b, cg, k, h, w]
// x (16,512,56,56) f32, w (16,16,9,56,56) f32, out (16,512,56,56) f32.
// Thread owns (b, gs, cg, h, w4): loads 9 weight float4 once, loops over 8 groups.

#define NB   16
#define NC   512
#define NG   32
#define NCG  16
#define NH   56
#define NW   56
#define NW4  14            // 56 / 4
#define PLANE   (NH * NW)  // 3136
#define GSPLIT  4
#define GPT     (NG / GSPLIT)   // 8 groups per thread
#define CSTRIDE (NCG * PLANE)   // x/out stride between consecutive groups (same cg)

__global__ __launch_bounds__(128, 8) void ska_kernel(
    const float* __restrict__ x,
    const float* __restrict__ wt,
    float* __restrict__ out)
{
    const int idx = blockIdx.x * 128 + threadIdx.x;
    // idx = (((b*GSPLIT + gs)*NCG + cg)*NH + h)*NW4 + w4
    const int w4 = idx % NW4;
    int t        = idx / NW4;
    const int h  = t % NH;  t /= NH;
    const int cg = t % NCG; t /= NCG;
    const int gs = t % GSPLIT;
    const int b  = t / GSPLIT;
    const int col = w4 * 4;

    // ---- 9 weight float4s, reused across the 8 groups ----
    const float* wbase = wt + ((((b * NCG + cg) * 9) * NH + h) * NW + col);
    float4 wk[9];
#pragma unroll
    for (int k = 0; k < 9; ++k)
        wk[k] = *reinterpret_cast<const float4*>(wbase + k * PLANE);

    const bool hm = (h > 0);
    const bool hp = (h < NH - 1);
    const bool wl = (col > 0);
    const bool wr = (col < NW - 4);

    // channel for group g0 = gs*GPT, this cg
    const int base = (b * NC + (gs * GPT) * NCG + cg) * PLANE + h * NW + col;
    const float* xc = x + base;
    float* oc       = out + base;

#pragma unroll 2
    for (int j = 0; j < GPT; ++j) {
        const float* xp = xc + j * CSTRIDE;
        float4 a = make_float4(0.f, 0.f, 0.f, 0.f);

#pragma unroll
        for (int di = 0; di < 3; ++di) {
            const bool v = (di == 1) || (di == 0 && hm) || (di == 2 && hp);
            const float* row = xp + (di - 1) * NW;
            float4 xm = make_float4(0.f, 0.f, 0.f, 0.f);
            float  xl = 0.f, xr = 0.f;
            if (v) {
                xm = *reinterpret_cast<const float4*>(row);
                if (wl) xl = row[-1];
                if (wr) xr = row[4];
            }

            const float4 w0 = wk[di * 3 + 0];
            const float4 w1 = wk[di * 3 + 1];
            const float4 w2 = wk[di * 3 + 2];

            // dj = -1
            a.x = fmaf(xl,   w0.x, a.x);
            a.y = fmaf(xm.x, w0.y, a.y);
            a.z = fmaf(xm.y, w0.z, a.z);
            a.w = fmaf(xm.z, w0.w, a.w);
            // dj = 0
            a.x = fmaf(xm.x, w1.x, a.x);
            a.y = fmaf(xm.y, w1.y, a.y);
            a.z = fmaf(xm.z, w1.z, a.z);
            a.w = fmaf(xm.w, w1.w, a.w);
            // dj = +1
            a.x = fmaf(xm.y, w2.x, a.x);
            a.y = fmaf(xm.z, w2.y, a.y);
            a.z = fmaf(xm.w, w2.z, a.z);
            a.w = fmaf(xr,   w2.w, a.w);
        }

        *reinterpret_cast<float4*>(oc + j * CSTRIDE) = a;
    }
}

extern "C" void kernel_launch(void* const* d_in, const int* in_sizes, int n_in,
                              void* d_out, int out_size)
{
    const float* x  = (const float*)d_in[0];
    const float* wt = (const float*)d_in[1];
    float* out      = (float*)d_out;

    const int total  = NB * GSPLIT * NCG * NH * NW4; // 802816 threads (multiple of 128)
    const int blocks = total / 128;                  // 6272
    ska_kernel<<<blocks, 128>>>(x, wt, out);
}

// round 3
// speedup vs baseline: 1.7017x; 1.1480x over previous
#include <cuda_runtime.h>

// SKA forward: out[b, g*16+cg, h, w] = sum_{k=0..8} x_pad[b, g*16+cg, h+di, w+dj] * w[b, cg, k, h, w]
// x (16,512,56,56) f32, w (16,16,9,56,56) f32, out (16,512,56,56) f32.
// Thread owns (b, gs, cg, h, w4): 9 weight float4 in regs, loops over 8 groups.
// Horizontal halo (xl/xr) via warp shuffle: consecutive lanes are consecutive w4
// in a row; row-wrap lanes coincide with image edges (value 0), only warp-edge
// lanes (0, 31) fall back to a predicated scalar load.

#define NB   16
#define NC   512
#define NG   32
#define NCG  16
#define NH   56
#define NW   56
#define NW4  14            // 56 / 4
#define PLANE   (NH * NW)  // 3136
#define GSPLIT  4
#define GPT     (NG / GSPLIT)   // 8 groups per thread
#define CSTRIDE (NCG * PLANE)   // stride between consecutive groups (same cg)

__global__ __launch_bounds__(128, 8) void ska_kernel(
    const float* __restrict__ x,
    const float* __restrict__ wt,
    float* __restrict__ out)
{
    const int idx = blockIdx.x * 128 + threadIdx.x;
    const int lane = threadIdx.x & 31;
    // idx = (((b*GSPLIT + gs)*NCG + cg)*NH + h)*NW4 + w4
    const int w4 = idx % NW4;
    int t        = idx / NW4;
    const int h  = t % NH;  t /= NH;
    const int cg = t % NCG; t /= NCG;
    const int gs = t % GSPLIT;
    const int b  = t / GSPLIT;
    const int col = w4 * 4;

    // ---- 9 weight float4s, reused across the 8 groups ----
    const float* wbase = wt + ((((b * NCG + cg) * 9) * NH + h) * NW + col);
    float4 wk[9];
#pragma unroll
    for (int k = 0; k < 9; ++k)
        wk[k] = *reinterpret_cast<const float4*>(wbase + k * PLANE);

    const bool hm = (h > 0);
    const bool hp = (h < NH - 1);
    const bool wl = (col > 0);
    const bool wr = (col < NW - 4);

    const int base = (b * NC + (gs * GPT) * NCG + cg) * PLANE + h * NW + col;
    const float* xc = x + base;
    float* oc       = out + base;

#pragma unroll 2
    for (int j = 0; j < GPT; ++j) {
        const float* xp = xc + j * CSTRIDE;
        float4 a = make_float4(0.f, 0.f, 0.f, 0.f);

#pragma unroll
        for (int di = 0; di < 3; ++di) {
            const bool v = (di == 1) || (di == 0 && hm) || (di == 2 && hp);
            const float* row = xp + (di - 1) * NW;

            float4 xm = make_float4(0.f, 0.f, 0.f, 0.f);
            if (v) xm = *reinterpret_cast<const float4*>(row);

            // horizontal halo via shuffle (all lanes participate)
            float xl = __shfl_up_sync(0xffffffffu,  xm.w, 1);
            float xr = __shfl_down_sync(0xffffffffu, xm.x, 1);
            // warp-edge lanes mid-row: real load (predicated, <=2 lanes active)
            if (lane == 0  && wl) xl = v ? row[-1] : 0.f;
            if (lane == 31 && wr) xr = v ? row[4]  : 0.f;
            // image edges: halo is zero
            if (!wl) xl = 0.f;
            if (!wr) xr = 0.f;

            const float4 w0 = wk[di * 3 + 0];
            const float4 w1 = wk[di * 3 + 1];
            const float4 w2 = wk[di * 3 + 2];

            // dj = -1
            a.x = fmaf(xl,   w0.x, a.x);
            a.y = fmaf(xm.x, w0.y, a.y);
            a.z = fmaf(xm.y, w0.z, a.z);
            a.w = fmaf(xm.z, w0.w, a.w);
            // dj = 0
            a.x = fmaf(xm.x, w1.x, a.x);
            a.y = fmaf(xm.y, w1.y, a.y);
            a.z = fmaf(xm.z, w1.z, a.z);
            a.w = fmaf(xm.w, w1.w, a.w);
            // dj = +1
            a.x = fmaf(xm.y, w2.x, a.x);
            a.y = fmaf(xm.z, w2.y, a.y);
            a.z = fmaf(xm.w, w2.z, a.z);
            a.w = fmaf(xr,   w2.w, a.w);
        }

        __stcs(reinterpret_cast<float4*>(oc + j * CSTRIDE), a);
    }
}

extern "C" void kernel_launch(void* const* d_in, const int* in_sizes, int n_in,
                              void* d_out, int out_size)
{
    const float* x  = (const float*)d_in[0];
    const float* wt = (const float*)d_in[1];
    float* out      = (float*)d_out;

    const int total  = NB * GSPLIT * NCG * NH * NW4; // 802816 threads
    const int blocks = total / 128;                  // 6272
    ska_kernel<<<blocks, 128>>>(x, wt, out);
}